// round 10
// baseline (speedup 1.0000x reference)
#include <cuda_runtime.h>
#include <cstdint>

// Problem constants
#define POOL 7
#define NUM_ROIS 256
#define H_IMG 128
#define W_IMG 128
#define C_IMG 1024
#define SCALE (1.0f / 16.0f)

// One CTA per (roi, cell), 128 threads, 8 channels (32 B) per thread per
// corner via LDG.256 (ld.global.nc.L2::evict_last.v8.b32 — the only form
// ptxas accepts evict_last on for sm_103a). evict_last keeps the 64 MB img
// L2-resident; streaming (evict-first) stores keep the 51 MB output from
// displacing it. Dead corners (zero lerp weight / clamped duplicate) are
// redirected to the live corner's address via SEL — same cache line, zero
// extra L2 bytes, bit-identical arithmetic (v + 0*(x - v) == v).

struct F8 { float4 a, b; };

__device__ __forceinline__ F8 ldg_el8(const float* p) {
    uint32_t r0, r1, r2, r3, r4, r5, r6, r7;
    asm volatile(
        "ld.global.nc.L2::evict_last.v8.b32 {%0,%1,%2,%3,%4,%5,%6,%7}, [%8];"
        : "=r"(r0), "=r"(r1), "=r"(r2), "=r"(r3),
          "=r"(r4), "=r"(r5), "=r"(r6), "=r"(r7)
        : "l"(p));
    F8 v;
    v.a.x = __uint_as_float(r0); v.a.y = __uint_as_float(r1);
    v.a.z = __uint_as_float(r2); v.a.w = __uint_as_float(r3);
    v.b.x = __uint_as_float(r4); v.b.y = __uint_as_float(r5);
    v.b.z = __uint_as_float(r6); v.b.w = __uint_as_float(r7);
    return v;
}

__global__ void __launch_bounds__(128, 8)
roi_pool_kernel(const float* __restrict__ img,
                const float* __restrict__ rois,
                float* __restrict__ out)
{
    const int cell = blockIdx.x;   // 0..48
    const int roi  = blockIdx.y;   // 0..255
    const int iy   = cell / POOL;
    const int ix   = cell % POOL;

    const float4 r = *(const float4*)(rois + roi * 4);
    const int x0 = (int)(r.x * SCALE);
    const int y0 = (int)(r.y * SCALE);
    const int w  = (int)(r.z * SCALE);
    const int h  = (int)(r.w * SCALE);

    // Match reference arithmetic order exactly
    const float sy = (float)iy * ((float)h / (float)POOL);
    const float sx = (float)ix * ((float)w / (float)POOL);
    const float fy = floorf(sy);
    const float fx = floorf(sx);
    const float ty = sy - fy;
    const float tx = sx - fx;
    const int y_lo = (int)fy;
    const int x_lo = (int)fx;
    const int y_hi = min(y_lo + 1, max(h - 1, 0));
    const int x_hi = min(x_lo + 1, max(w - 1, 0));
    const int gy0 = min(max(y0 + y_lo, 0), H_IMG - 1);
    int       gy1 = min(max(y0 + y_hi, 0), H_IMG - 1);
    const int gx0 = min(max(x0 + x_lo, 0), W_IMG - 1);
    int       gx1 = min(max(x0 + x_hi, 0), W_IMG - 1);

    // Branchless dead-load redirection (SEL, no branches).
    gx1 = (tx != 0.0f) ? gx1 : gx0;
    gy1 = (ty != 0.0f) ? gy1 : gy0;

    const int c = threadIdx.x;              // 8-float chunk index 0..127
    const int co = c << 3;                  // float offset within channel dim

    const float* p00 = img + ((size_t)(gy0 * W_IMG + gx0) << 10) + co;
    const float* p01 = img + ((size_t)(gy0 * W_IMG + gx1) << 10) + co;
    const float* p10 = img + ((size_t)(gy1 * W_IMG + gx0) << 10) + co;
    const float* p11 = img + ((size_t)(gy1 * W_IMG + gx1) << 10) + co;

    const F8 v00 = ldg_el8(p00);
    const F8 v01 = ldg_el8(p01);
    const F8 v10 = ldg_el8(p10);
    const F8 v11 = ldg_el8(p11);

    float4 oa, ob;
    #define LERP(O, H00, H01, H10, H11, F)                          \
        {                                                           \
            float top = H00.F + tx * (H01.F - H00.F);               \
            float bot = H10.F + tx * (H11.F - H10.F);               \
            O.F = top + ty * (bot - top);                           \
        }
    LERP(oa, v00.a, v01.a, v10.a, v11.a, x)
    LERP(oa, v00.a, v01.a, v10.a, v11.a, y)
    LERP(oa, v00.a, v01.a, v10.a, v11.a, z)
    LERP(oa, v00.a, v01.a, v10.a, v11.a, w)
    LERP(ob, v00.b, v01.b, v10.b, v11.b, x)
    LERP(ob, v00.b, v01.b, v10.b, v11.b, y)
    LERP(ob, v00.b, v01.b, v10.b, v11.b, z)
    LERP(ob, v00.b, v01.b, v10.b, v11.b, w)
    #undef LERP

    // Streaming (evict-first) stores: output never displaces img in L2.
    float4* dst = (float4*)(out + (((size_t)(roi * (POOL * POOL) + cell)) << 10) + co);
    __stcs(dst,     oa);
    __stcs(dst + 1, ob);
}

extern "C" void kernel_launch(void* const* d_in, const int* in_sizes, int n_in,
                              void* d_out, int out_size)
{
    const float* img  = (const float*)d_in[0];
    const float* rois = (const float*)d_in[1];
    float* out = (float*)d_out;

    dim3 grid(POOL * POOL, NUM_ROIS);
    roi_pool_kernel<<<grid, 128>>>(img, rois, out);
}